// round 17
// baseline (speedup 1.0000x reference)
#include <cuda_runtime.h>
#include <cstdint>

#define B_DIM  64
#define S_DIM  2048
#define D_DIM  6
#define H_DIM  8
#define NC     32
#define CHUNK  8             // timesteps per chunk
#define NCHUNK 256           // chunks per chain
#define GRP    16            // chunks per scan group
#define NGRP   16            // groups per chain

// ---- scratch (device globals; no allocation allowed) ----
// Champion layouts: AoS everywhere.
__device__ float g_psi  [(size_t)B_DIM * S_DIM * H_DIM * NC];   // [b][t][h][k] 134 MB
__device__ float g_chunk[(size_t)B_DIM * H_DIM * NCHUNK * NC];  // [b][h][c][k]
__device__ float g_carry[(size_t)B_DIM * H_DIM * NCHUNK * NC];  // [b][h][c][k]

// ---- Cl(4,1) sign machinery (validated R1) ----
__host__ __device__ constexpr int cpopc(int v) {
    int c = 0;
    for (int i = 0; i < 5; ++i) c += (v >> i) & 1;
    return c;
}
__host__ __device__ constexpr bool sign_neg(int a, int b) {
    int s = 0;
    for (int t = 1; t < 5; ++t) s += cpopc((a >> t) & b);
    if (a & b & 16) s += 1;           // metric: e5*e5 = -1
    return (s & 1) != 0;
}

// scalar GP (kC only)
__device__ __forceinline__ void gp(const float* __restrict__ a,
                                   const float* __restrict__ b,
                                   float* __restrict__ o) {
#pragma unroll
    for (int k = 0; k < NC; ++k) {
        float acc = 0.f;
#pragma unroll
        for (int i = 0; i < NC; ++i) {
            if (sign_neg(i, i ^ k)) acc = fmaf(-a[i], b[i ^ k], acc);
            else                    acc = fmaf( a[i], b[i ^ k], acc);
        }
        o[k] = acc;
    }
}

__device__ __forceinline__ float rnorm(const float* v) {   // 1/|v| via MUFU.RSQ
    float ss = 0.f;
#pragma unroll
    for (int k = 0; k < NC; ++k) ss = fmaf(v[k], v[k], ss);
    return rsqrtf(ss + 1e-30f);
}

__device__ __forceinline__ void load32(const float* __restrict__ p, float* v) {
#pragma unroll
    for (int q = 0; q < 8; ++q) {
        float4 t = reinterpret_cast<const float4*>(p)[q];
        v[4 * q + 0] = t.x; v[4 * q + 1] = t.y;
        v[4 * q + 2] = t.z; v[4 * q + 3] = t.w;
    }
}
__device__ __forceinline__ void store32(float* __restrict__ p, const float* v) {
#pragma unroll
    for (int q = 0; q < 8; ++q) {
        float4 t;
        t.x = v[4 * q + 0]; t.y = v[4 * q + 1];
        t.z = v[4 * q + 2]; t.w = v[4 * q + 3];
        reinterpret_cast<float4*>(p)[q] = t;
    }
}

// ---- f32x2 packed helpers ----
__device__ __forceinline__ unsigned long long pack2(float lo, float hi) {
    unsigned long long r;
    asm("mov.b64 %0, {%1, %2};" : "=l"(r) : "f"(lo), "f"(hi));
    return r;
}
__device__ __forceinline__ void unpack2(unsigned long long v, float& lo, float& hi) {
    asm("mov.b64 {%0, %1}, %2;" : "=f"(lo), "=f"(hi) : "l"(v));
}
__device__ __forceinline__ unsigned long long ffma2(unsigned long long a,
                                                    unsigned long long b,
                                                    unsigned long long c) {
    unsigned long long d;
    asm("fma.rn.f32x2 %0, %1, %2, %3;" : "=l"(d) : "l"(a), "l"(b), "l"(c));
    return d;
}

// ---- paired GP core: one output component from pair operands ----
// o[k] = sum_r s(2r,2r^k) * [ Ap[r] dot2 (k&1 ? Bs : Bn)[r ^ (k>>1)] ]
// where Ap[r] = (a_2r, (-1)^popc(r) * a_2r+1), Bn/Bs natural/swapped b-pairs.
// Pair-internal sign identity: sign(2r+1,(2r+1)^k) = sign(2r,2r^k)*(-1)^popc(r).
template <int K>
__device__ __forceinline__ float gp_pair_out(const unsigned long long* __restrict__ Ap,
                                             const unsigned long long* __restrict__ Bn,
                                             const unsigned long long* __restrict__ Bs) {
    unsigned long long pos = 0ull, neg = 0ull;
#pragma unroll
    for (int r = 0; r < 16; ++r) {
        const int p = r ^ (K >> 1);
        unsigned long long op = (K & 1) ? Bs[p] : Bn[p];
        if (sign_neg(2 * r, (2 * r) ^ K)) neg = ffma2(Ap[r], op, neg);
        else                              pos = ffma2(Ap[r], op, pos);
    }
    float pl, ph, nl, nh;
    unpack2(pos, pl, ph);
    unpack2(neg, nl, nh);
    return (pl + ph) - (nl + nh);
}

__device__ __forceinline__ void build_ap(const float* __restrict__ a,
                                         unsigned long long* __restrict__ Ap) {
#pragma unroll
    for (int r = 0; r < 16; ++r) {
        float hi = (cpopc(r) & 1) ? -a[2 * r + 1] : a[2 * r + 1];
        Ap[r] = pack2(a[2 * r], hi);
    }
}

// ---- per-lane sign setup for shuffle GP (validated R1) ----
__device__ __forceinline__ void lane_sign(int k, unsigned& smask, bool& gneg) {
    int m = 0;
#pragma unroll
    for (int p = 0; p < 5; ++p) {
        int bit = __popc(k & ((1 << p) - 1)) & 1;
        m |= bit << p;
    }
    m ^= (k & 16);
    smask = 0u;
#pragma unroll
    for (int i = 0; i < NC; ++i)
        smask |= (unsigned)(__popc(i & m) & 1) << i;
    int pc = __popc(k);
    gneg = (((pc * (pc - 1) / 2) + ((k >> 4) & 1)) & 1) != 0;
}

// one shuffle-GP step with normalization: r <- N(GP(a, r)); a pre-negated by gneg
__device__ __forceinline__ float shfl_gp_norm(float a, float r, unsigned smask) {
    float acc = 0.f;
#pragma unroll
    for (int i = 0; i < NC; ++i) {
        float va = __shfl_sync(0xffffffffu, a, i);
        float vr = __shfl_xor_sync(0xffffffffu, r, i);
        unsigned sb = (smask << (31 - i)) & 0x80000000u;
        va = __uint_as_float(__float_as_uint(va) ^ sb);
        acc = fmaf(va, vr, acc);
    }
    float ss = acc * acc;
#pragma unroll
    for (int o = 16; o > 0; o >>= 1) ss += __shfl_xor_sync(0xffffffffu, ss, o);
    return acc * rsqrtf(ss + 1e-30f);
}

// ---- Kernel AB: fused delta + chunk products + intra-chunk prefixes ----
// Champion mapping (thread per (b,h,c)), AoS float4 psi stores, NO per-step
// norm (validated), PAIRED-FFMA2 GP with P held only as Pn/Ps pairs.
__global__ void kAB(const float* __restrict__ x,
                    const float* __restrict__ Win,
                    const float* __restrict__ bin) {
    __shared__ float sW[D_DIM * H_DIM * NC];   // 6 KB
    __shared__ float sB[H_DIM * NC];
    for (int i = threadIdx.x; i < D_DIM * H_DIM * NC; i += blockDim.x) sW[i] = Win[i];
    for (int i = threadIdx.x; i < H_DIM * NC; i += blockDim.x) sB[i] = bin[i];
    __syncthreads();

    int tid = blockIdx.x * blockDim.x + threadIdx.x;   // 0 .. 131071
    int c = tid & (NCHUNK - 1);
    int h = (tid >> 8) & (H_DIM - 1);
    int b = tid >> 11;
    const float* bcol = sB + h * NC;
    const float* wcol = sW + h * NC;

    unsigned long long Pn[16], Ps[16];   // P as natural/swapped pairs
    float o[NC];                         // step output (also last chunk total)

#pragma unroll 1
    for (int j = 0; j < CHUNK; ++j) {
        int t = c * CHUNK + j;
        const float* xr = x + (b * S_DIM + t) * D_DIM;
        float2 x01 = reinterpret_cast<const float2*>(xr)[0];
        float2 x23 = reinterpret_cast<const float2*>(xr)[1];
        float2 x45 = reinterpret_cast<const float2*>(xr)[2];
        float xv[D_DIM] = {x01.x, x01.y, x23.x, x23.y, x45.x, x45.y};

        float u[NC];
#pragma unroll
        for (int k = 0; k < NC; ++k) {
            float a = bcol[k];
#pragma unroll
            for (int d = 0; d < D_DIM; ++d)
                a = fmaf(xv[d], wcol[d * (H_DIM * NC) + k], a);
            u[k] = a;
        }
        u[0] += 1.f;                      // delta direction; norm skipped (cancels)

        if (j == 0) {
#pragma unroll
            for (int k = 0; k < NC; ++k) o[k] = u[k];
        } else {
            unsigned long long Ap[16];
            build_ap(u, Ap);              // multiplier = newer delta (LEFT)
#pragma unroll
            for (int k = 0; k < NC; ++k) {
                // constexpr K via manual dispatch through the unrolled loop
                switch (k) {
#define GPCASE(K) case K: o[K] = gp_pair_out<K>(Ap, Pn, Ps); break;
                    GPCASE(0)  GPCASE(1)  GPCASE(2)  GPCASE(3)
                    GPCASE(4)  GPCASE(5)  GPCASE(6)  GPCASE(7)
                    GPCASE(8)  GPCASE(9)  GPCASE(10) GPCASE(11)
                    GPCASE(12) GPCASE(13) GPCASE(14) GPCASE(15)
                    GPCASE(16) GPCASE(17) GPCASE(18) GPCASE(19)
                    GPCASE(20) GPCASE(21) GPCASE(22) GPCASE(23)
                    GPCASE(24) GPCASE(25) GPCASE(26) GPCASE(27)
                    GPCASE(28) GPCASE(29) GPCASE(30) GPCASE(31)
#undef GPCASE
                }
            }
        }
        // rebuild P pairs from o
#pragma unroll
        for (int m = 0; m < 16; ++m) {
            Pn[m] = pack2(o[2 * m], o[2 * m + 1]);
            Ps[m] = pack2(o[2 * m + 1], o[2 * m]);
        }
        store32(g_psi + ((size_t)(b * S_DIM + t) * H_DIM + h) * NC, o);   // AoS
    }
    // normalize chunk total once (conditioning for the scan), store [b][h][c][k]
    float inv = rnorm(o);
    float Pnrm[NC];
#pragma unroll
    for (int k = 0; k < NC; ++k) Pnrm[k] = o[k] * inv;
    store32(g_chunk + ((b * H_DIM + h) * NCHUNK + c) * NC, Pnrm);
}

// ---- Kernel C: full per-chain scan in ONE block (validated fused form) ----
__global__ void __launch_bounds__(512) kC() {
    __shared__ float s_scan[NCHUNK * 33];   // padded rows: bank-conflict-free
    __shared__ float s_tot[NGRP * NC];      // group exclusive carries

    int chain = blockIdx.x;                 // b*8 + h
    int tid = threadIdx.x;
    int wid = tid >> 5;
    int k = tid & 31;
    unsigned smask; bool gneg;
    lane_sign(k, smask, gneg);
    int cb = chain * NCHUNK * NC;

    // phase 1: warp g scans its 16-chunk group (inclusive) into smem
    {
        int g = wid;
        float r = g_chunk[cb + (g * GRP) * NC + k];
        s_scan[(g * GRP) * 33 + k] = r;
#pragma unroll
        for (int j = 1; j < GRP; ++j) {
            float a = g_chunk[cb + (g * GRP + j) * NC + k];
            if (gneg) a = -a;
            r = shfl_gp_norm(a, r, smask);
            s_scan[(g * GRP + j) * 33 + k] = r;
        }
    }
    __syncthreads();

    // phase 2: warp 0 exclusive-scans the 16 group totals
    if (wid == 0) {
        float r = (k == 0) ? 1.f : 0.f;     // identity rotor
#pragma unroll
        for (int g = 0; g < NGRP; ++g) {
            s_tot[g * NC + k] = r;
            float a = s_scan[(g * GRP + GRP - 1) * 33 + k];
            if (gneg) a = -a;
            r = shfl_gp_norm(a, r, smask);
        }
    }
    __syncthreads();

    // phase 3: threads 0..255 compute per-chunk exclusive carries (no norm)
    if (tid < NCHUNK) {
        int c = tid, g = c >> 4;
        float G[NC], O[NC];
#pragma unroll
        for (int q = 0; q < NC; ++q) G[q] = s_tot[g * NC + q];
        if ((c & (GRP - 1)) == 0) {
#pragma unroll
            for (int q = 0; q < NC; ++q) O[q] = G[q];
        } else {
            float A[NC];
#pragma unroll
            for (int q = 0; q < NC; ++q) A[q] = s_scan[(c - 1) * 33 + q];
            gp(A, G, O);                    // within-group inclusive (newer) on LEFT
        }
        store32(g_carry + (chain * NCHUNK + c) * NC, O);   // AoS champion layout
    }
}

// ---- kDE: fused expand + projection, champion mapping + PAIRED GP +
// streamed matvec (no O[] array; norm folded in after via linearity) ----
__global__ void kDE(const float* __restrict__ Wout,
                    const float* __restrict__ bout,
                    float* __restrict__ out) {
    __shared__ __align__(16) float sW[H_DIM * NC * NC];   // 32 KB
    __shared__ float sb[NC];
    for (int i = threadIdx.x; i < H_DIM * NC * NC; i += blockDim.x) sW[i] = Wout[i];
    if (threadIdx.x < NC) sb[threadIdx.x] = bout[threadIdx.x];
    __syncthreads();

    int tid = blockIdx.x * blockDim.x + threadIdx.x;   // row = b*S + t
    size_t row = (size_t)tid;
    int t = tid & (S_DIM - 1);
    int b = tid >> 11;
    int c = t >> 3;                                    // CHUNK=8

    unsigned long long acc2[16];
#pragma unroll
    for (int q = 0; q < 16; ++q) acc2[q] = pack2(sb[2 * q], sb[2 * q + 1]);

#pragma unroll 1
    for (int h = 0; h < H_DIM; ++h) {
        unsigned long long Ap[16], Cn[16], Cs[16];
        {
            float A[NC], Cv[NC];
            load32(g_psi + (row * H_DIM + h) * NC, A);          // 1KB/thread stream
            load32(g_carry + (((size_t)(b * H_DIM + h)) * NCHUNK + c) * NC, Cv);
            build_ap(A, Ap);              // multiplier = prefix (LEFT)
#pragma unroll
            for (int m = 0; m < 16; ++m) {
                Cn[m] = pack2(Cv[2 * m], Cv[2 * m + 1]);
                Cs[m] = pack2(Cv[2 * m + 1], Cv[2 * m]);
            }
        }

        const float* wh = sW + h * (NC * NC);
        unsigned long long macc2[16];
#pragma unroll
        for (int q = 0; q < 16; ++q) macc2[q] = 0ull;
        float ssa = 0.f, ssb = 0.f;

#pragma unroll
        for (int k = 0; k < NC; ++k) {
            float ok;
            switch (k) {
#define GPCASE(K) case K: ok = gp_pair_out<K>(Ap, Cn, Cs); break;
                GPCASE(0)  GPCASE(1)  GPCASE(2)  GPCASE(3)
                GPCASE(4)  GPCASE(5)  GPCASE(6)  GPCASE(7)
                GPCASE(8)  GPCASE(9)  GPCASE(10) GPCASE(11)
                GPCASE(12) GPCASE(13) GPCASE(14) GPCASE(15)
                GPCASE(16) GPCASE(17) GPCASE(18) GPCASE(19)
                GPCASE(20) GPCASE(21) GPCASE(22) GPCASE(23)
                GPCASE(24) GPCASE(25) GPCASE(26) GPCASE(27)
                GPCASE(28) GPCASE(29) GPCASE(30) GPCASE(31)
#undef GPCASE
                default: ok = 0.f;
            }
            if (k & 1) ssb = fmaf(ok, ok, ssb);
            else       ssa = fmaf(ok, ok, ssa);

            unsigned long long ok2 = pack2(ok, ok);
            const ulonglong2* wr = reinterpret_cast<const ulonglong2*>(wh + k * NC);
#pragma unroll
            for (int q = 0; q < 8; ++q) {
                ulonglong2 wv = wr[q];    // warp-uniform smem address -> broadcast
                macc2[2 * q + 0] = ffma2(ok2, wv.x, macc2[2 * q + 0]);
                macc2[2 * q + 1] = ffma2(ok2, wv.y, macc2[2 * q + 1]);
            }
        }

        float inv = rsqrtf(ssa + ssb + 1e-30f);   // psi unit-scale before bias add
        unsigned long long inv2 = pack2(inv, inv);
#pragma unroll
        for (int q = 0; q < 16; ++q) acc2[q] = ffma2(inv2, macc2[q], acc2[q]);
    }

    float res[NC];
    float ss = 0.f;
#pragma unroll
    for (int q = 0; q < 16; ++q) {
        float lo, hi;
        unpack2(acc2[q], lo, hi);
        res[2 * q] = lo; res[2 * q + 1] = hi;
        ss = fmaf(lo, lo, fmaf(hi, hi, ss));
    }
    float inv = rsqrtf(ss + 1e-30f);
    float4* orow = reinterpret_cast<float4*>(out + row * NC);
#pragma unroll
    for (int q = 0; q < 8; ++q) {
        float4 v;
        v.x = res[4 * q + 0] * inv; v.y = res[4 * q + 1] * inv;
        v.z = res[4 * q + 2] * inv; v.w = res[4 * q + 3] * inv;
        orow[q] = v;
    }
}

extern "C" void kernel_launch(void* const* d_in, const int* in_sizes, int n_in,
                              void* d_out, int out_size) {
    const float* x    = (const float*)d_in[0];
    const float* Win  = (const float*)d_in[1];
    const float* bin  = (const float*)d_in[2];
    const float* Wout = (const float*)d_in[3];
    const float* bout = (const float*)d_in[4];
    float* out = (float*)d_out;

    kAB<<<(B_DIM * H_DIM * NCHUNK) / 128, 128>>>(x, Win, bin);
    kC<<<B_DIM * H_DIM, 512>>>();
    kDE<<<(B_DIM * S_DIM) / 128, 128>>>(Wout, bout, out);
}